// round 13
// baseline (speedup 1.0000x reference)
#include <cuda_runtime.h>
#include <cuda_fp16.h>

#define N_NODES 100000
#define N_EDGES 1600000
#define IN_CH   256
#define HID_CH  128
#define OUT_CH  64
#define NB_SCAN ((N_NODES + 255) / 256)   // 391

// ---------------- scratch (device globals; no cudaMalloc allowed) ----------
__device__ int      g_cnt     [N_NODES];
__device__ int      g_rowstart[N_NODES];
__device__ int      g_cursor  [N_NODES];
__device__ int      g_part    [512];
__device__ int2     g_csr     [N_EDGES];          // (src, weight-as-int)
__device__ float    g_dinv    [N_NODES];
__device__ __half   g_h1h[(size_t)N_NODES * HID_CH];   // x @ W1   (fp16)
__device__ __half   g_h2h[(size_t)N_NODES * OUT_CH];   // relu(a1) @ W2 (fp16)
__device__ unsigned g_W1p[(IN_CH / 2) * HID_CH];   // fp16 packed, 2 k per word
__device__ unsigned g_W2p[(HID_CH / 2) * OUT_CH];
__device__ int      g_is64;

// ---------------- prep: zero counters + dtype detect ------------------------
__global__ void zero_detect_kernel(const unsigned* __restrict__ w) {
    int n = blockIdx.x * blockDim.x + threadIdx.x;
    if (n < N_NODES) g_cnt[n] = 0;
    if (n == 0) {
        int is64 = 1;
        for (int i = 0; i < 64; i++)
            if (w[2 * i + 1] != 0u) { is64 = 0; break; }
        g_is64 = is64;
    }
}

// 8 edges per thread
__global__ void count_deg_kernel(const void* __restrict__ ei) {
    int t = blockIdx.x * blockDim.x + threadIdx.x;
    if (t >= N_EDGES / 8) return;
    int d[8];
    if (g_is64) {
        const longlong2* p =
            (const longlong2*)((const long long*)ei + N_EDGES);
#pragma unroll
        for (int q = 0; q < 4; q++) {
            longlong2 a = p[4 * t + q];
            d[2 * q] = (int)a.x; d[2 * q + 1] = (int)a.y;
        }
    } else {
        const int4* p = (const int4*)((const int*)ei + N_EDGES);
        int4 a = p[2 * t], b = p[2 * t + 1];
        d[0] = a.x; d[1] = a.y; d[2] = a.z; d[3] = a.w;
        d[4] = b.x; d[5] = b.y; d[6] = b.z; d[7] = b.w;
    }
#pragma unroll
    for (int q = 0; q < 8; q++) atomicAdd(&g_cnt[d[q]], 1);
}

// ---------------- W pack (fp16, 2 k per word, n-fastest source) -------------
__global__ void wpack_kernel(const float* __restrict__ W1,
                             const float* __restrict__ W2) {
    int i = blockIdx.x * blockDim.x + threadIdx.x;
    if (i < (IN_CH / 2) * HID_CH) {
        int k2 = i / HID_CH, n = i % HID_CH;
        float w0 = W1[(size_t)(2 * k2) * HID_CH + n];
        float w1 = W1[(size_t)(2 * k2 + 1) * HID_CH + n];
        __half2 p = __floats2half2_rn(w0, w1);
        g_W1p[i] = *reinterpret_cast<unsigned*>(&p);
    }
    if (i < (HID_CH / 2) * OUT_CH) {
        int k2 = i / OUT_CH, n = i % OUT_CH;
        float w0 = W2[(size_t)(2 * k2) * OUT_CH + n];
        float w1 = W2[(size_t)(2 * k2 + 1) * OUT_CH + n];
        __half2 p = __floats2half2_rn(w0, w1);
        g_W2p[i] = *reinterpret_cast<unsigned*>(&p);
    }
}

// ---------------- scans (dinv fused into scan1; scan2 fused into scan23) ----
__global__ void scan1_kernel() {
    __shared__ int sm[256];
    int tid = threadIdx.x;
    int i = blockIdx.x * 256 + tid;
    int v = (i < N_NODES) ? g_cnt[i] : 0;
    if (i < N_NODES) g_dinv[i] = rsqrtf((float)(v + 1));   // +1 self-loop
    sm[tid] = v;
    __syncthreads();
#pragma unroll
    for (int off = 1; off < 256; off <<= 1) {
        int t = (tid >= off) ? sm[tid - off] : 0;
        __syncthreads();
        sm[tid] += t;
        __syncthreads();
    }
    if (i < N_NODES) g_rowstart[i] = sm[tid] - v;
    if (tid == 255) g_part[blockIdx.x] = sm[tid];
}

__global__ void scan23_kernel() {
    __shared__ int sm[256];
    int tid = threadIdx.x;
    int v = 0;
    for (int i = tid; i < blockIdx.x; i += 256) v += g_part[i];
    sm[tid] = v;
    __syncthreads();
#pragma unroll
    for (int off = 128; off > 0; off >>= 1) {
        if (tid < off) sm[tid] += sm[tid + off];
        __syncthreads();
    }
    int base = sm[0];
    int i = blockIdx.x * 256 + tid;
    if (i < N_NODES) {
        int r = g_rowstart[i] + base;
        g_rowstart[i] = r;
        g_cursor[i] = r;
    }
}

// ---------------- CSR fill (4 edges per thread) ------------------------------
__global__ void fill_csr_kernel(const void* __restrict__ ei) {
    int t = blockIdx.x * blockDim.x + threadIdx.x;
    if (t >= N_EDGES / 4) return;
    int s[4], d[4];
    if (g_is64) {
        const longlong2* ps = (const longlong2*)ei;
        const longlong2* pd = (const longlong2*)((const long long*)ei + N_EDGES);
#pragma unroll
        for (int q = 0; q < 2; q++) {
            longlong2 a = ps[2 * t + q], b = pd[2 * t + q];
            s[2 * q] = (int)a.x; s[2 * q + 1] = (int)a.y;
            d[2 * q] = (int)b.x; d[2 * q + 1] = (int)b.y;
        }
    } else {
        int4 a = ((const int4*)ei)[t];
        int4 b = ((const int4*)((const int*)ei + N_EDGES))[t];
        s[0] = a.x; s[1] = a.y; s[2] = a.z; s[3] = a.w;
        d[0] = b.x; d[1] = b.y; d[2] = b.z; d[3] = b.w;
    }
#pragma unroll
    for (int q = 0; q < 4; q++) {
        float w = g_dinv[s[q]] * g_dinv[d[q]];
        int slot = atomicAdd(&g_cursor[d[q]], 1);
        g_csr[slot] = make_int2(s[q], __float_as_int(w));
    }
}

// ---------------- tensor-core mma helper -------------------------------------
__device__ __forceinline__ void mma_f16(float* c, const unsigned* a,
                                        unsigned b0, unsigned b1) {
    asm volatile(
        "mma.sync.aligned.m16n8k16.row.col.f32.f16.f16.f32 "
        "{%0,%1,%2,%3},{%4,%5,%6,%7},{%8,%9},{%0,%1,%2,%3};"
        : "+f"(c[0]), "+f"(c[1]), "+f"(c[2]), "+f"(c[3])
        : "r"(a[0]), "r"(a[1]), "r"(a[2]), "r"(a[3]), "r"(b0), "r"(b1));
}

// ---------------- GEMM1: h1(fp16) = x(fp32) @ W1 -----------------------------
__global__ __launch_bounds__(256)
void gemm1_kernel(const float* __restrict__ A,
                  const unsigned* __restrict__ Wp,
                  __half* __restrict__ out, int M) {
    constexpr int K = IN_CH, NC = HID_CH;
    constexpr int STRIDE = 20;
    constexpr int WARPS_M = 4;      // WARPS_N = 2
    constexpr int MT = 2;

    __shared__ unsigned As[128 * STRIDE];
    __shared__ unsigned Bs[NC * STRIDE];

    int tid = threadIdx.x, wid = tid >> 5, lane = tid & 31;
    int g = lane >> 2, t4 = lane & 3;
    int warp_m = (wid % WARPS_M) * (MT * 16);
    int warp_n = (wid / WARPS_M) * 64;
    int m0 = blockIdx.x * 128;

    float acc[MT][8][4];
#pragma unroll
    for (int mt = 0; mt < MT; mt++)
#pragma unroll
        for (int nt = 0; nt < 8; nt++)
#pragma unroll
            for (int i = 0; i < 4; i++) acc[mt][nt][i] = 0.0f;

    for (int kk = 0; kk < K; kk += 32) {
#pragma unroll
        for (int i = 0; i < 4; i++) {
            int idx = i * 256 + tid;
            int r = idx >> 3, c4 = idx & 7;
            int gm = m0 + r;
            uint2 w = make_uint2(0u, 0u);
            if (gm < M) {
                float4 v = *(const float4*)(A + (size_t)gm * K + kk + c4 * 4);
                __half2 p0 = __floats2half2_rn(v.x, v.y);
                __half2 p1 = __floats2half2_rn(v.z, v.w);
                w.x = *reinterpret_cast<unsigned*>(&p0);
                w.y = *reinterpret_cast<unsigned*>(&p1);
            }
            *(uint2*)&As[r * STRIDE + c4 * 2] = w;
        }
        {
            // B chunk: (32/2) * 128 = 2048 packed words -> 8 x 256
            const unsigned* wp = Wp + (size_t)(kk >> 1) * NC;
#pragma unroll
            for (int i = 0; i < 8; i++) {
                int idx = i * 256 + tid;
                int n = idx & 127, k2 = idx >> 7;
                Bs[n * STRIDE + k2] = wp[idx];
            }
        }
        __syncthreads();

#pragma unroll
        for (int ks = 0; ks < 2; ks++) {
            unsigned a[MT][4];
#pragma unroll
            for (int mt = 0; mt < MT; mt++) {
                int r0 = (warp_m + mt * 16 + g) * STRIDE + ks * 8 + t4;
                int r1 = (warp_m + mt * 16 + g + 8) * STRIDE + ks * 8 + t4;
                a[mt][0] = As[r0];     a[mt][1] = As[r1];
                a[mt][2] = As[r0 + 4]; a[mt][3] = As[r1 + 4];
            }
#pragma unroll
            for (int nt = 0; nt < 8; nt++) {
                int bi = (warp_n + nt * 8 + g) * STRIDE + ks * 8 + t4;
                unsigned b0 = Bs[bi], b1 = Bs[bi + 4];
#pragma unroll
                for (int mt = 0; mt < MT; mt++)
                    mma_f16(acc[mt][nt], a[mt], b0, b1);
            }
        }
        __syncthreads();
    }

#pragma unroll
    for (int mt = 0; mt < MT; mt++) {
        int r0 = m0 + warp_m + mt * 16 + g;
        int r1 = r0 + 8;
#pragma unroll
        for (int nt = 0; nt < 8; nt++) {
            int col = warp_n + nt * 8 + t4 * 2;
            if (r0 < M)
                *(__half2*)(out + (size_t)r0 * NC + col) =
                    __floats2half2_rn(acc[mt][nt][0], acc[mt][nt][1]);
            if (r1 < M)
                *(__half2*)(out + (size_t)r1 * NC + col) =
                    __floats2half2_rn(acc[mt][nt][2], acc[mt][nt][3]);
        }
    }
}

// ---------------- 8x fp16 -> 8x fp32 unpack ----------------------------------
__device__ __forceinline__ void h8_acc(uint4 u, float w, float* acc) {
    float2 f0 = __half22float2(*reinterpret_cast<__half2*>(&u.x));
    float2 f1 = __half22float2(*reinterpret_cast<__half2*>(&u.y));
    float2 f2 = __half22float2(*reinterpret_cast<__half2*>(&u.z));
    float2 f3 = __half22float2(*reinterpret_cast<__half2*>(&u.w));
    acc[0] += w * f0.x; acc[1] += w * f0.y;
    acc[2] += w * f1.x; acc[3] += w * f1.y;
    acc[4] += w * f2.x; acc[5] += w * f2.y;
    acc[6] += w * f3.x; acc[7] += w * f3.y;
}

__device__ __forceinline__ void h4_acc(uint2 u, float w, float* acc) {
    float2 f0 = __half22float2(*reinterpret_cast<__half2*>(&u.x));
    float2 f1 = __half22float2(*reinterpret_cast<__half2*>(&u.y));
    acc[0] += w * f0.x; acc[1] += w * f0.y;
    acc[2] += w * f1.x; acc[3] += w * f1.y;
}

// ---------------- FUSED: agg1 (CSR) + relu + GEMM2 --------------------------
// Phase 1: 16-lane subgroups, uint4 row loads, 8-edge unroll (MLP ~8).
// Phase 2: mma vs W2 on the smem A-tile (STRIDE-20 fragment layout).
__global__ __launch_bounds__(256)
void agg1_gemm2_kernel(const float* __restrict__ b1,
                       const unsigned* __restrict__ Wp,
                       __half* __restrict__ out, int M) {
    constexpr int STRIDE = 20;
    constexpr int NC = OUT_CH;      // 64

    __shared__ unsigned As[4][128 * STRIDE];   // 4 k-chunks of 32
    __shared__ unsigned Bs[NC * STRIDE];

    int tid = threadIdx.x, wid = tid >> 5, lane = tid & 31;
    int g = lane >> 2, t4 = lane & 3;
    int m0 = blockIdx.x * 128;

    // ---- phase 1: 16 lanes per node, channels 8*hl .. 8*hl+7 ----
    int half = lane >> 4;           // 0/1: which node of the pair
    int hl   = lane & 15;           // lane within subgroup
    float4 bA = ((const float4*)b1)[2 * hl];
    float4 bB = ((const float4*)b1)[2 * hl + 1];
    int chunk = hl >> 2;            // channel block of 32
    int word  = (hl & 3) * 4;       // word offset within chunk row

#pragma unroll 1
    for (int i = 0; i < 8; i++) {
        int r = wid * 16 + i * 2 + half;
        int node = m0 + r;
        uint4 u = make_uint4(0u, 0u, 0u, 0u);
        if (node < M) {
            int beg = g_rowstart[node];
            int cnt = g_cnt[node];
            float acc[8];
#pragma unroll
            for (int k = 0; k < 8; k++) acc[k] = 0.0f;
            int j = 0;
            for (; j + 7 < cnt; j += 8) {
                int2 e[8];
                uint4 v[8];
#pragma unroll
                for (int q = 0; q < 8; q++)
                    e[q] = __ldg(&g_csr[beg + j + q]);
#pragma unroll
                for (int q = 0; q < 8; q++)
                    v[q] = __ldg((const uint4*)(g_h1h + (size_t)e[q].x * HID_CH) + hl);
#pragma unroll
                for (int q = 0; q < 8; q++)
                    h8_acc(v[q], __int_as_float(e[q].y), acc);
            }
            for (; j + 3 < cnt; j += 4) {
                int2 e0 = __ldg(&g_csr[beg + j]);
                int2 e1 = __ldg(&g_csr[beg + j + 1]);
                int2 e2 = __ldg(&g_csr[beg + j + 2]);
                int2 e3 = __ldg(&g_csr[beg + j + 3]);
                uint4 v0 = __ldg((const uint4*)(g_h1h + (size_t)e0.x * HID_CH) + hl);
                uint4 v1 = __ldg((const uint4*)(g_h1h + (size_t)e1.x * HID_CH) + hl);
                uint4 v2 = __ldg((const uint4*)(g_h1h + (size_t)e2.x * HID_CH) + hl);
                uint4 v3 = __ldg((const uint4*)(g_h1h + (size_t)e3.x * HID_CH) + hl);
                h8_acc(v0, __int_as_float(e0.y), acc);
                h8_acc(v1, __int_as_float(e1.y), acc);
                h8_acc(v2, __int_as_float(e2.y), acc);
                h8_acc(v3, __int_as_float(e3.y), acc);
            }
            for (; j < cnt; j++) {
                int2 e = __ldg(&g_csr[beg + j]);
                uint4 v = __ldg((const uint4*)(g_h1h + (size_t)e.x * HID_CH) + hl);
                h8_acc(v, __int_as_float(e.y), acc);
            }
            float di = g_dinv[node];
            float sw = di * di;
            uint4 hv = *((const uint4*)(g_h1h + (size_t)node * HID_CH) + hl);
            h8_acc(hv, sw, acc);
            acc[0] = fmaxf(acc[0] + bA.x, 0.f);
            acc[1] = fmaxf(acc[1] + bA.y, 0.f);
            acc[2] = fmaxf(acc[2] + bA.z, 0.f);
            acc[3] = fmaxf(acc[3] + bA.w, 0.f);
            acc[4] = fmaxf(acc[4] + bB.x, 0.f);
            acc[5] = fmaxf(acc[5] + bB.y, 0.f);
            acc[6] = fmaxf(acc[6] + bB.z, 0.f);
            acc[7] = fmaxf(acc[7] + bB.w, 0.f);
            __half2 p0 = __floats2half2_rn(acc[0], acc[1]);
            __half2 p1 = __floats2half2_rn(acc[2], acc[3]);
            __half2 p2 = __floats2half2_rn(acc[4], acc[5]);
            __half2 p3 = __floats2half2_rn(acc[6], acc[7]);
            u.x = *reinterpret_cast<unsigned*>(&p0);
            u.y = *reinterpret_cast<unsigned*>(&p1);
            u.z = *reinterpret_cast<unsigned*>(&p2);
            u.w = *reinterpret_cast<unsigned*>(&p3);
        }
        *(uint4*)&As[chunk][r * STRIDE + word] = u;
    }
    __syncthreads();

    // ---- phase 2: GEMM vs W2 (K=128, NC=64; 8 warps over M) ----
    int warp_m = wid * 16;
    float acc[8][4];
#pragma unroll
    for (int nt = 0; nt < 8; nt++)
#pragma unroll
        for (int i = 0; i < 4; i++) acc[nt][i] = 0.0f;

#pragma unroll
    for (int c = 0; c < 4; c++) {
        {
            // B chunk: (32/2) * 64 = 1024 packed words -> 4 x 256
            const unsigned* wp = Wp + (size_t)(c * 16) * NC;
#pragma unroll
            for (int i = 0; i < 4; i++) {
                int idx = i * 256 + tid;
                int n = idx & 63, k2 = idx >> 6;
                Bs[n * STRIDE + k2] = wp[idx];
            }
        }
        __syncthreads();

#pragma unroll
        for (int ks = 0; ks < 2; ks++) {
            unsigned a[4];
            int r0 = (warp_m + g) * STRIDE + ks * 8 + t4;
            int r1 = (warp_m + g + 8) * STRIDE + ks * 8 + t4;
            a[0] = As[c][r0];     a[1] = As[c][r1];
            a[2] = As[c][r0 + 4]; a[3] = As[c][r1 + 4];
#pragma unroll
            for (int nt = 0; nt < 8; nt++) {
                int bi = (nt * 8 + g) * STRIDE + ks * 8 + t4;
                unsigned b0 = Bs[bi], b1 = Bs[bi + 4];
                mma_f16(acc[nt], a, b0, b1);
            }
        }
        __syncthreads();
    }

    // ---- epilogue: h2 fp16 ----
    int r0 = m0 + warp_m + g;
    int r1 = r0 + 8;
#pragma unroll
    for (int nt = 0; nt < 8; nt++) {
        int col = nt * 8 + t4 * 2;
        if (r0 < M)
            *(__half2*)(out + (size_t)r0 * NC + col) =
                __floats2half2_rn(acc[nt][0], acc[nt][1]);
        if (r1 < M)
            *(__half2*)(out + (size_t)r1 * NC + col) =
                __floats2half2_rn(acc[nt][2], acc[nt][3]);
    }
}

// ---------------- agg2: 16 lanes/node (uint2), 2 nodes/warp, 8-edge unroll --
__global__ __launch_bounds__(256)
void agg2_kernel(const float* __restrict__ b2, float* __restrict__ out) {
    int t = blockIdx.x * blockDim.x + threadIdx.x;
    int node = t >> 4;
    int hl = t & 15;                // channels 4*hl .. 4*hl+3
    if (node >= N_NODES) return;
    int beg = g_rowstart[node];
    int cnt = g_cnt[node];

    float acc[4];
#pragma unroll
    for (int k = 0; k < 4; k++) acc[k] = 0.0f;
    int j = 0;
    for (; j + 7 < cnt; j += 8) {
        int2 e[8];
        uint2 v[8];
#pragma unroll
        for (int q = 0; q < 8; q++)
            e[q] = __ldg(&g_csr[beg + j + q]);
#pragma unroll
        for (int q = 0; q < 8; q++)
            v[q] = __ldg((const uint2*)(g_h2h + (size_t)e[q].x * OUT_CH) + hl);
#pragma unroll
        for (int q = 0; q < 8; q++)
            h4_acc(v[q], __int_as_float(e[q].y), acc);
    }
    for (; j + 3 < cnt; j += 4) {
        int2 e0 = __ldg(&g_csr[beg + j]);
        int2 e1 = __ldg(&g_csr[beg + j + 1]);
        int2 e2 = __ldg(&g_csr[beg + j + 2]);
        int2 e3 = __ldg(&g_csr[beg + j + 3]);
        uint2 v0 = __ldg((const uint2*)(g_h2h + (size_t)e0.x * OUT_CH) + hl);
        uint2 v1 = __ldg((const uint2*)(g_h2h + (size_t)e1.x * OUT_CH) + hl);
        uint2 v2 = __ldg((const uint2*)(g_h2h + (size_t)e2.x * OUT_CH) + hl);
        uint2 v3 = __ldg((const uint2*)(g_h2h + (size_t)e3.x * OUT_CH) + hl);
        h4_acc(v0, __int_as_float(e0.y), acc);
        h4_acc(v1, __int_as_float(e1.y), acc);
        h4_acc(v2, __int_as_float(e2.y), acc);
        h4_acc(v3, __int_as_float(e3.y), acc);
    }
    for (; j < cnt; j++) {
        int2 e = __ldg(&g_csr[beg + j]);
        uint2 v = __ldg((const uint2*)(g_h2h + (size_t)e.x * OUT_CH) + hl);
        h4_acc(v, __int_as_float(e.y), acc);
    }
    float di = g_dinv[node];
    float sw = di * di;
    uint2 hv = *((const uint2*)(g_h2h + (size_t)node * OUT_CH) + hl);
    h4_acc(hv, sw, acc);
    float4 b = ((const float4*)b2)[hl];
    float4 o = make_float4(acc[0] + b.x, acc[1] + b.y,
                           acc[2] + b.z, acc[3] + b.w);
    *(float4*)(out + (size_t)node * OUT_CH + hl * 4) = o;
}

// ---------------- launch ----------------------------------------------------
extern "C" void kernel_launch(void* const* d_in, const int* in_sizes, int n_in,
                              void* d_out, int out_size) {
    const float* x  = (const float*)d_in[0];
    const void*  ei = d_in[1];
    const float* W1 = (const float*)d_in[2];
    const float* b1 = (const float*)d_in[3];
    const float* W2 = (const float*)d_in[4];
    const float* b2 = (const float*)d_in[5];
    float* out = (float*)d_out;

    __half *p_h1h, *p_h2h;
    unsigned *p_W1p, *p_W2p;
    cudaGetSymbolAddress((void**)&p_h1h, g_h1h);
    cudaGetSymbolAddress((void**)&p_h2h, g_h2h);
    cudaGetSymbolAddress((void**)&p_W1p, g_W1p);
    cudaGetSymbolAddress((void**)&p_W2p, g_W2p);

    static cudaStream_t s_side = nullptr;
    static cudaEvent_t  s_fork = nullptr, s_join = nullptr;
    if (s_side == nullptr) {
        cudaStreamCreateWithFlags(&s_side, cudaStreamNonBlocking);
        cudaEventCreateWithFlags(&s_fork, cudaEventDisableTiming);
        cudaEventCreateWithFlags(&s_join, cudaEventDisableTiming);
    }

    // ---- fork: CSR-build branch concurrent with wpack + GEMM1 ----
    cudaEventRecord(s_fork, 0);
    cudaStreamWaitEvent(s_side, s_fork, 0);

    // submission order puts gemm1 at launch index 3 (profiling visibility);
    // stream ordering keeps the dependency chains identical.
    zero_detect_kernel<<<NB_SCAN, 256, 0, s_side>>>((const unsigned*)ei);   // 0
    count_deg_kernel<<<(N_EDGES / 8 + 255) / 256, 256, 0, s_side>>>(ei);    // 1
    wpack_kernel<<<((IN_CH / 2) * HID_CH + 255) / 256, 256>>>(W1, W2);      // 2
    gemm1_kernel<<<(N_NODES + 127) / 128, 256>>>(x, p_W1p, p_h1h, N_NODES); // 3
    scan1_kernel<<<NB_SCAN, 256, 0, s_side>>>();                            // 4
    scan23_kernel<<<NB_SCAN, 256, 0, s_side>>>();                           // 5
    fill_csr_kernel<<<(N_EDGES / 4 + 255) / 256, 256, 0, s_side>>>(ei);     // 6
    cudaEventRecord(s_join, s_side);

    cudaStreamWaitEvent(0, s_join, 0);

    // fused agg1 + relu + GEMM2 -> h2
    agg1_gemm2_kernel<<<(N_NODES + 127) / 128, 256>>>(b1, p_W2p, p_h2h, N_NODES);
    // final aggregation -> out
    agg2_kernel<<<(N_NODES * 16 + 255) / 256, 256>>>(b2, out);
}

// round 14
// speedup vs baseline: 1.0043x; 1.0043x over previous
#include <cuda_runtime.h>
#include <cuda_fp16.h>

#define N_NODES 100000
#define N_EDGES 1600000
#define IN_CH   256
#define HID_CH  128
#define OUT_CH  64
#define NB_SCAN ((N_NODES + 255) / 256)   // 391

// ---------------- scratch (device globals; no cudaMalloc allowed) ----------
__device__ int      g_cnt     [N_NODES];
__device__ int      g_rowstart[N_NODES];
__device__ int      g_cursor  [N_NODES];
__device__ int      g_part    [512];
__device__ int2     g_csr     [N_EDGES];          // (src, weight-as-int)
__device__ float    g_dinv    [N_NODES];
__device__ __half   g_h1h[(size_t)N_NODES * HID_CH];   // x @ W1   (fp16)
__device__ __half   g_h2h[(size_t)N_NODES * OUT_CH];   // relu(a1) @ W2 (fp16)
// W packed fp16, FRAGMENT-MAJOR: per 32-k chunk, per 8-col tile, per ks,
// lane (g*4+t4) holds {w, w+4} word pair contiguously (LDS.64 per fragment).
__device__ unsigned g_W1p[(IN_CH / 2) * HID_CH];
__device__ unsigned g_W2p[(HID_CH / 2) * OUT_CH];
__device__ int      g_is64;

// ---------------- prep: zero counters + dtype detect ------------------------
__global__ void zero_detect_kernel(const unsigned* __restrict__ w) {
    int n = blockIdx.x * blockDim.x + threadIdx.x;
    if (n < N_NODES) g_cnt[n] = 0;
    if (n == 0) {
        int is64 = 1;
        for (int i = 0; i < 64; i++)
            if (w[2 * i + 1] != 0u) { is64 = 0; break; }
        g_is64 = is64;
    }
}

// 8 edges per thread
__global__ void count_deg_kernel(const void* __restrict__ ei) {
    int t = blockIdx.x * blockDim.x + threadIdx.x;
    if (t >= N_EDGES / 8) return;
    int d[8];
    if (g_is64) {
        const longlong2* p =
            (const longlong2*)((const long long*)ei + N_EDGES);
#pragma unroll
        for (int q = 0; q < 4; q++) {
            longlong2 a = p[4 * t + q];
            d[2 * q] = (int)a.x; d[2 * q + 1] = (int)a.y;
        }
    } else {
        const int4* p = (const int4*)((const int*)ei + N_EDGES);
        int4 a = p[2 * t], b = p[2 * t + 1];
        d[0] = a.x; d[1] = a.y; d[2] = a.z; d[3] = a.w;
        d[4] = b.x; d[5] = b.y; d[6] = b.z; d[7] = b.w;
    }
#pragma unroll
    for (int q = 0; q < 8; q++) atomicAdd(&g_cnt[d[q]], 1);
}

// ---------------- W pack: fp16, fragment-major layout ------------------------
// dest index: chunk*(16*NC) + (n>>3)*128 + ks*64 + ((n&7)*4 + t4)*2 + j
//   where k2 in chunk: w = k2&15, ks = w>>3, j = (w>>2)&1, t4 = w&3.
__global__ void wpack_kernel(const float* __restrict__ W1,
                             const float* __restrict__ W2) {
    int i = blockIdx.x * blockDim.x + threadIdx.x;
    if (i < (IN_CH / 2) * HID_CH) {
        int k2 = i / HID_CH, n = i % HID_CH;
        float w0 = W1[(size_t)(2 * k2) * HID_CH + n];
        float w1 = W1[(size_t)(2 * k2 + 1) * HID_CH + n];
        __half2 p = __floats2half2_rn(w0, w1);
        int chunk = k2 >> 4, w = k2 & 15;
        int ks = w >> 3, j = (w >> 2) & 1, t4 = w & 3;
        int idx = chunk * (16 * HID_CH) + (n >> 3) * 128 + ks * 64 +
                  ((n & 7) * 4 + t4) * 2 + j;
        g_W1p[idx] = *reinterpret_cast<unsigned*>(&p);
    }
    if (i < (HID_CH / 2) * OUT_CH) {
        int k2 = i / OUT_CH, n = i % OUT_CH;
        float w0 = W2[(size_t)(2 * k2) * OUT_CH + n];
        float w1 = W2[(size_t)(2 * k2 + 1) * OUT_CH + n];
        __half2 p = __floats2half2_rn(w0, w1);
        int chunk = k2 >> 4, w = k2 & 15;
        int ks = w >> 3, j = (w >> 2) & 1, t4 = w & 3;
        int idx = chunk * (16 * OUT_CH) + (n >> 3) * 128 + ks * 64 +
                  ((n & 7) * 4 + t4) * 2 + j;
        g_W2p[idx] = *reinterpret_cast<unsigned*>(&p);
    }
}

// ---------------- scans (dinv fused into scan1; scan2 fused into scan23) ----
__global__ void scan1_kernel() {
    __shared__ int sm[256];
    int tid = threadIdx.x;
    int i = blockIdx.x * 256 + tid;
    int v = (i < N_NODES) ? g_cnt[i] : 0;
    if (i < N_NODES) g_dinv[i] = rsqrtf((float)(v + 1));   // +1 self-loop
    sm[tid] = v;
    __syncthreads();
#pragma unroll
    for (int off = 1; off < 256; off <<= 1) {
        int t = (tid >= off) ? sm[tid - off] : 0;
        __syncthreads();
        sm[tid] += t;
        __syncthreads();
    }
    if (i < N_NODES) g_rowstart[i] = sm[tid] - v;
    if (tid == 255) g_part[blockIdx.x] = sm[tid];
}

__global__ void scan23_kernel() {
    __shared__ int sm[256];
    int tid = threadIdx.x;
    int v = 0;
    for (int i = tid; i < blockIdx.x; i += 256) v += g_part[i];
    sm[tid] = v;
    __syncthreads();
#pragma unroll
    for (int off = 128; off > 0; off >>= 1) {
        if (tid < off) sm[tid] += sm[tid + off];
        __syncthreads();
    }
    int base = sm[0];
    int i = blockIdx.x * 256 + tid;
    if (i < N_NODES) {
        int r = g_rowstart[i] + base;
        g_rowstart[i] = r;
        g_cursor[i] = r;
    }
}

// ---------------- CSR fill (4 edges per thread) ------------------------------
__global__ void fill_csr_kernel(const void* __restrict__ ei) {
    int t = blockIdx.x * blockDim.x + threadIdx.x;
    if (t >= N_EDGES / 4) return;
    int s[4], d[4];
    if (g_is64) {
        const longlong2* ps = (const longlong2*)ei;
        const longlong2* pd = (const longlong2*)((const long long*)ei + N_EDGES);
#pragma unroll
        for (int q = 0; q < 2; q++) {
            longlong2 a = ps[2 * t + q], b = pd[2 * t + q];
            s[2 * q] = (int)a.x; s[2 * q + 1] = (int)a.y;
            d[2 * q] = (int)b.x; d[2 * q + 1] = (int)b.y;
        }
    } else {
        int4 a = ((const int4*)ei)[t];
        int4 b = ((const int4*)((const int*)ei + N_EDGES))[t];
        s[0] = a.x; s[1] = a.y; s[2] = a.z; s[3] = a.w;
        d[0] = b.x; d[1] = b.y; d[2] = b.z; d[3] = b.w;
    }
#pragma unroll
    for (int q = 0; q < 4; q++) {
        float w = g_dinv[s[q]] * g_dinv[d[q]];
        int slot = atomicAdd(&g_cursor[d[q]], 1);
        g_csr[slot] = make_int2(s[q], __float_as_int(w));
    }
}

// ---------------- tensor-core mma helper -------------------------------------
__device__ __forceinline__ void mma_f16(float* c, const unsigned* a,
                                        unsigned b0, unsigned b1) {
    asm volatile(
        "mma.sync.aligned.m16n8k16.row.col.f32.f16.f16.f32 "
        "{%0,%1,%2,%3},{%4,%5,%6,%7},{%8,%9},{%0,%1,%2,%3};"
        : "+f"(c[0]), "+f"(c[1]), "+f"(c[2]), "+f"(c[3])
        : "r"(a[0]), "r"(a[1]), "r"(a[2]), "r"(a[3]), "r"(b0), "r"(b1));
}

// ---------------- GEMM1: h1(fp16) = x(fp32) @ W1 -----------------------------
__global__ __launch_bounds__(256)
void gemm1_kernel(const float* __restrict__ A,
                  const unsigned* __restrict__ Wp,
                  __half* __restrict__ out, int M) {
    constexpr int K = IN_CH, NC = HID_CH;
    constexpr int STRIDE = 20;
    constexpr int WARPS_M = 4;      // WARPS_N = 2
    constexpr int MT = 2;
    constexpr int BWORDS = 16 * NC; // 2048 words per chunk (frag-major flat)

    __shared__ unsigned As[128 * STRIDE];
    __shared__ unsigned Bs[BWORDS];

    int tid = threadIdx.x, wid = tid >> 5, lane = tid & 31;
    int g = lane >> 2, t4 = lane & 3;
    int warp_m = (wid % WARPS_M) * (MT * 16);
    int warp_n = (wid / WARPS_M) * 64;
    int bct0 = warp_n >> 3;         // first col-tile for this warp
    int m0 = blockIdx.x * 128;

    float acc[MT][8][4];
#pragma unroll
    for (int mt = 0; mt < MT; mt++)
#pragma unroll
        for (int nt = 0; nt < 8; nt++)
#pragma unroll
            for (int i = 0; i < 4; i++) acc[mt][nt][i] = 0.0f;

    for (int kk = 0; kk < K; kk += 32) {
#pragma unroll
        for (int i = 0; i < 4; i++) {
            int idx = i * 256 + tid;
            int r = idx >> 3, c4 = idx & 7;
            int gm = m0 + r;
            uint2 w = make_uint2(0u, 0u);
            if (gm < M) {
                float4 v = *(const float4*)(A + (size_t)gm * K + kk + c4 * 4);
                __half2 p0 = __floats2half2_rn(v.x, v.y);
                __half2 p1 = __floats2half2_rn(v.z, v.w);
                w.x = *reinterpret_cast<unsigned*>(&p0);
                w.y = *reinterpret_cast<unsigned*>(&p1);
            }
            *(uint2*)&As[r * STRIDE + c4 * 2] = w;
        }
        {
            // B chunk: frag-major flat copy, 2048 words = 512 uint4
            const uint4* wp = (const uint4*)(Wp + (size_t)(kk >> 5) * BWORDS);
            uint4* bs = (uint4*)Bs;
            bs[tid]       = wp[tid];
            bs[tid + 256] = wp[tid + 256];
        }
        __syncthreads();

#pragma unroll
        for (int ks = 0; ks < 2; ks++) {
            unsigned a[MT][4];
#pragma unroll
            for (int mt = 0; mt < MT; mt++) {
                int r0 = (warp_m + mt * 16 + g) * STRIDE + ks * 8 + t4;
                int r1 = (warp_m + mt * 16 + g + 8) * STRIDE + ks * 8 + t4;
                a[mt][0] = As[r0];     a[mt][1] = As[r1];
                a[mt][2] = As[r0 + 4]; a[mt][3] = As[r1 + 4];
            }
#pragma unroll
            for (int nt = 0; nt < 8; nt++) {
                uint2 b = *(const uint2*)&Bs[(bct0 + nt) * 128 + ks * 64 + lane * 2];
#pragma unroll
                for (int mt = 0; mt < MT; mt++)
                    mma_f16(acc[mt][nt], a[mt], b.x, b.y);
            }
        }
        __syncthreads();
    }

#pragma unroll
    for (int mt = 0; mt < MT; mt++) {
        int r0 = m0 + warp_m + mt * 16 + g;
        int r1 = r0 + 8;
#pragma unroll
        for (int nt = 0; nt < 8; nt++) {
            int col = warp_n + nt * 8 + t4 * 2;
            if (r0 < M)
                *(__half2*)(out + (size_t)r0 * NC + col) =
                    __floats2half2_rn(acc[mt][nt][0], acc[mt][nt][1]);
            if (r1 < M)
                *(__half2*)(out + (size_t)r1 * NC + col) =
                    __floats2half2_rn(acc[mt][nt][2], acc[mt][nt][3]);
        }
    }
}

// ---------------- 8x fp16 -> 8x fp32 unpack ----------------------------------
__device__ __forceinline__ void h8_acc(uint4 u, float w, float* acc) {
    float2 f0 = __half22float2(*reinterpret_cast<__half2*>(&u.x));
    float2 f1 = __half22float2(*reinterpret_cast<__half2*>(&u.y));
    float2 f2 = __half22float2(*reinterpret_cast<__half2*>(&u.z));
    float2 f3 = __half22float2(*reinterpret_cast<__half2*>(&u.w));
    acc[0] += w * f0.x; acc[1] += w * f0.y;
    acc[2] += w * f1.x; acc[3] += w * f1.y;
    acc[4] += w * f2.x; acc[5] += w * f2.y;
    acc[6] += w * f3.x; acc[7] += w * f3.y;
}

// ---------------- FUSED: agg1 (CSR) + relu + GEMM2 --------------------------
__global__ __launch_bounds__(256)
void agg1_gemm2_kernel(const float* __restrict__ b1,
                       const unsigned* __restrict__ Wp,
                       __half* __restrict__ out, int M) {
    constexpr int STRIDE = 20;
    constexpr int NC = OUT_CH;      // 64
    constexpr int BWORDS = 16 * NC; // 1024 words per chunk

    __shared__ unsigned As[4][128 * STRIDE];   // 4 k-chunks of 32
    __shared__ unsigned Bs[BWORDS];

    int tid = threadIdx.x, wid = tid >> 5, lane = tid & 31;
    int g = lane >> 2, t4 = lane & 3;
    int m0 = blockIdx.x * 128;

    // ---- phase 1: 16 lanes per node, channels 8*hl .. 8*hl+7 ----
    int half = lane >> 4;
    int hl   = lane & 15;
    float4 bA = ((const float4*)b1)[2 * hl];
    float4 bB = ((const float4*)b1)[2 * hl + 1];
    int chunk = hl >> 2;
    int word  = (hl & 3) * 4;

#pragma unroll 1
    for (int i = 0; i < 8; i++) {
        int r = wid * 16 + i * 2 + half;
        int node = m0 + r;
        uint4 u = make_uint4(0u, 0u, 0u, 0u);
        if (node < M) {
            int beg = g_rowstart[node];
            int cnt = g_cnt[node];
            float acc[8];
#pragma unroll
            for (int k = 0; k < 8; k++) acc[k] = 0.0f;
            int j = 0;
            for (; j + 7 < cnt; j += 8) {
                int2 e[8];
                uint4 v[8];
#pragma unroll
                for (int q = 0; q < 8; q++)
                    e[q] = __ldg(&g_csr[beg + j + q]);
#pragma unroll
                for (int q = 0; q < 8; q++)
                    v[q] = __ldg((const uint4*)(g_h1h + (size_t)e[q].x * HID_CH) + hl);
#pragma unroll
                for (int q = 0; q < 8; q++)
                    h8_acc(v[q], __int_as_float(e[q].y), acc);
            }
            for (; j + 3 < cnt; j += 4) {
                int2 e0 = __ldg(&g_csr[beg + j]);
                int2 e1 = __ldg(&g_csr[beg + j + 1]);
                int2 e2 = __ldg(&g_csr[beg + j + 2]);
                int2 e3 = __ldg(&g_csr[beg + j + 3]);
                uint4 v0 = __ldg((const uint4*)(g_h1h + (size_t)e0.x * HID_CH) + hl);
                uint4 v1 = __ldg((const uint4*)(g_h1h + (size_t)e1.x * HID_CH) + hl);
                uint4 v2 = __ldg((const uint4*)(g_h1h + (size_t)e2.x * HID_CH) + hl);
                uint4 v3 = __ldg((const uint4*)(g_h1h + (size_t)e3.x * HID_CH) + hl);
                h8_acc(v0, __int_as_float(e0.y), acc);
                h8_acc(v1, __int_as_float(e1.y), acc);
                h8_acc(v2, __int_as_float(e2.y), acc);
                h8_acc(v3, __int_as_float(e3.y), acc);
            }
            for (; j < cnt; j++) {
                int2 e = __ldg(&g_csr[beg + j]);
                uint4 v = __ldg((const uint4*)(g_h1h + (size_t)e.x * HID_CH) + hl);
                h8_acc(v, __int_as_float(e.y), acc);
            }
            float di = g_dinv[node];
            float sw = di * di;
            uint4 hv = *((const uint4*)(g_h1h + (size_t)node * HID_CH) + hl);
            h8_acc(hv, sw, acc);
            acc[0] = fmaxf(acc[0] + bA.x, 0.f);
            acc[1] = fmaxf(acc[1] + bA.y, 0.f);
            acc[2] = fmaxf(acc[2] + bA.z, 0.f);
            acc[3] = fmaxf(acc[3] + bA.w, 0.f);
            acc[4] = fmaxf(acc[4] + bB.x, 0.f);
            acc[5] = fmaxf(acc[5] + bB.y, 0.f);
            acc[6] = fmaxf(acc[6] + bB.z, 0.f);
            acc[7] = fmaxf(acc[7] + bB.w, 0.f);
            __half2 p0 = __floats2half2_rn(acc[0], acc[1]);
            __half2 p1 = __floats2half2_rn(acc[2], acc[3]);
            __half2 p2 = __floats2half2_rn(acc[4], acc[5]);
            __half2 p3 = __floats2half2_rn(acc[6], acc[7]);
            u.x = *reinterpret_cast<unsigned*>(&p0);
            u.y = *reinterpret_cast<unsigned*>(&p1);
            u.z = *reinterpret_cast<unsigned*>(&p2);
            u.w = *reinterpret_cast<unsigned*>(&p3);
        }
        *(uint4*)&As[chunk][r * STRIDE + word] = u;
    }
    __syncthreads();

    // ---- phase 2: GEMM vs W2 (K=128, NC=64; 8 warps over M) ----
    int warp_m = wid * 16;
    float acc[8][4];
#pragma unroll
    for (int nt = 0; nt < 8; nt++)
#pragma unroll
        for (int i = 0; i < 4; i++) acc[nt][i] = 0.0f;

#pragma unroll
    for (int c = 0; c < 4; c++) {
        {
            // B chunk: frag-major flat copy, 1024 words = 256 uint4
            const uint4* wp = (const uint4*)(Wp + (size_t)c * BWORDS);
            ((uint4*)Bs)[tid] = wp[tid];
        }
        __syncthreads();

#pragma unroll
        for (int ks = 0; ks < 2; ks++) {
            unsigned a[4];
            int r0 = (warp_m + g) * STRIDE + ks * 8 + t4;
            int r1 = (warp_m + g + 8) * STRIDE + ks * 8 + t4;
            a[0] = As[c][r0];     a[1] = As[c][r1];
            a[2] = As[c][r0 + 4]; a[3] = As[c][r1 + 4];
#pragma unroll
            for (int nt = 0; nt < 8; nt++) {
                uint2 b = *(const uint2*)&Bs[nt * 128 + ks * 64 + lane * 2];
                mma_f16(acc[nt], a, b.x, b.y);
            }
        }
        __syncthreads();
    }

    // ---- epilogue: h2 fp16 ----
    int r0 = m0 + warp_m + g;
    int r1 = r0 + 8;
#pragma unroll
    for (int nt = 0; nt < 8; nt++) {
        int col = nt * 8 + t4 * 2;
        if (r0 < M)
            *(__half2*)(out + (size_t)r0 * NC + col) =
                __floats2half2_rn(acc[nt][0], acc[nt][1]);
        if (r1 < M)
            *(__half2*)(out + (size_t)r1 * NC + col) =
                __floats2half2_rn(acc[nt][2], acc[nt][3]);
    }
}

// ---------------- agg2: 8 lanes/node, uint4, 8-edge unroll (R12 winner) -----
__global__ __launch_bounds__(256)
void agg2_kernel(const float* __restrict__ b2, float* __restrict__ out) {
    int t = blockIdx.x * blockDim.x + threadIdx.x;
    int node = t >> 3;
    int l8 = t & 7;                 // channels 8*l8 .. 8*l8+7
    if (node >= N_NODES) return;
    int beg = g_rowstart[node];
    int cnt = g_cnt[node];

    float acc[8];
#pragma unroll
    for (int k = 0; k < 8; k++) acc[k] = 0.0f;
    int j = 0;
    for (; j + 7 < cnt; j += 8) {
        int2 e[8];
        uint4 v[8];
#pragma unroll
        for (int q = 0; q < 8; q++)
            e[q] = __ldg(&g_csr[beg + j + q]);
#pragma unroll
        for (int q = 0; q < 8; q++)
            v[q] = __ldg((const uint4*)(g_h2h + (size_t)e[q].x * OUT_CH) + l8);
#pragma unroll
        for (int q = 0; q < 8; q++)
            h8_acc(v[q], __int_as_float(e[q].y), acc);
    }
    for (; j + 3 < cnt; j += 4) {
        int2 e0 = __ldg(&g_csr[beg + j]);
        int2 e1 = __ldg(&g_csr[beg + j + 1]);
        int2 e2 = __ldg(&g_csr[beg + j + 2]);
        int2 e3 = __ldg(&g_csr[beg + j + 3]);
        uint4 v0 = __ldg((const uint4*)(g_h2h + (size_t)e0.x * OUT_CH) + l8);
        uint4 v1 = __ldg((const uint4*)(g_h2h + (size_t)e1.x * OUT_CH) + l8);
        uint4 v2 = __ldg((const uint4*)(g_h2h + (size_t)e2.x * OUT_CH) + l8);
        uint4 v3 = __ldg((const uint4*)(g_h2h + (size_t)e3.x * OUT_CH) + l8);
        h8_acc(v0, __int_as_float(e0.y), acc);
        h8_acc(v1, __int_as_float(e1.y), acc);
        h8_acc(v2, __int_as_float(e2.y), acc);
        h8_acc(v3, __int_as_float(e3.y), acc);
    }
    for (; j < cnt; j++) {
        int2 e = __ldg(&g_csr[beg + j]);
        uint4 v = __ldg((const uint4*)(g_h2h + (size_t)e.x * OUT_CH) + l8);
        h8_acc(v, __int_as_float(e.y), acc);
    }
    float di = g_dinv[node];
    float sw = di * di;
    uint4 hv = *((const uint4*)(g_h2h + (size_t)node * OUT_CH) + l8);
    h8_acc(hv, sw, acc);
    float4 bA = ((const float4*)b2)[2 * l8];
    float4 bB = ((const float4*)b2)[2 * l8 + 1];
    float4 o0 = make_float4(acc[0] + bA.x, acc[1] + bA.y,
                            acc[2] + bA.z, acc[3] + bA.w);
    float4 o1 = make_float4(acc[4] + bB.x, acc[5] + bB.y,
                            acc[6] + bB.z, acc[7] + bB.w);
    float* dst = out + (size_t)node * OUT_CH + l8 * 8;
    *(float4*)dst = o0;
    *(float4*)(dst + 4) = o1;
}

// ---------------- launch ----------------------------------------------------
extern "C" void kernel_launch(void* const* d_in, const int* in_sizes, int n_in,
                              void* d_out, int out_size) {
    const float* x  = (const float*)d_in[0];
    const void*  ei = d_in[1];
    const float* W1 = (const float*)d_in[2];
    const float* b1 = (const float*)d_in[3];
    const float* W2 = (const float*)d_in[4];
    const float* b2 = (const float*)d_in[5];
    float* out = (float*)d_out;

    __half *p_h1h, *p_h2h;
    unsigned *p_W1p, *p_W2p;
    cudaGetSymbolAddress((void**)&p_h1h, g_h1h);
    cudaGetSymbolAddress((void**)&p_h2h, g_h2h);
    cudaGetSymbolAddress((void**)&p_W1p, g_W1p);
    cudaGetSymbolAddress((void**)&p_W2p, g_W2p);

    static cudaStream_t s_side = nullptr;
    static cudaEvent_t  s_fork = nullptr, s_join = nullptr;
    if (s_side == nullptr) {
        cudaStreamCreateWithFlags(&s_side, cudaStreamNonBlocking);
        cudaEventCreateWithFlags(&s_fork, cudaEventDisableTiming);
        cudaEventCreateWithFlags(&s_join, cudaEventDisableTiming);
    }

    // ---- fork: CSR-build branch concurrent with wpack + GEMM1 ----
    cudaEventRecord(s_fork, 0);
    cudaStreamWaitEvent(s_side, s_fork, 0);

    zero_detect_kernel<<<NB_SCAN, 256, 0, s_side>>>((const unsigned*)ei);   // 0
    count_deg_kernel<<<(N_EDGES / 8 + 255) / 256, 256, 0, s_side>>>(ei);    // 1
    wpack_kernel<<<((IN_CH / 2) * HID_CH + 255) / 256, 256>>>(W1, W2);      // 2
    gemm1_kernel<<<(N_NODES + 127) / 128, 256>>>(x, p_W1p, p_h1h, N_NODES); // 3
    scan1_kernel<<<NB_SCAN, 256, 0, s_side>>>();                            // 4
    scan23_kernel<<<NB_SCAN, 256, 0, s_side>>>();                           // 5
    fill_csr_kernel<<<(N_EDGES / 4 + 255) / 256, 256, 0, s_side>>>(ei);     // 6
    cudaEventRecord(s_join, s_side);

    cudaStreamWaitEvent(0, s_join, 0);

    // fused agg1 + relu + GEMM2 -> h2
    agg1_gemm2_kernel<<<(N_NODES + 127) / 128, 256>>>(b1, p_W2p, p_h2h, N_NODES);
    // final aggregation -> out
    agg2_kernel<<<(N_NODES * 8 + 255) / 256, 256>>>(b2, out);
}

// round 15
// speedup vs baseline: 1.0380x; 1.0335x over previous
#include <cuda_runtime.h>
#include <cuda_fp16.h>

#define N_NODES 100000
#define N_EDGES 1600000
#define IN_CH   256
#define HID_CH  128
#define OUT_CH  64
#define NB_SCAN ((N_NODES + 255) / 256)   // 391

// ---------------- scratch (device globals; no cudaMalloc allowed) ----------
__device__ int      g_cnt     [N_NODES];
__device__ int      g_rowstart[N_NODES];
__device__ int      g_cursor  [N_NODES];
__device__ int      g_part    [512];
__device__ int2     g_csr     [N_EDGES];          // (src, weight-as-int)
__device__ float    g_dinv    [N_NODES];
__device__ __half   g_h1h[(size_t)N_NODES * HID_CH];   // x @ W1   (fp16)
__device__ __half   g_h2h[(size_t)N_NODES * OUT_CH];   // relu(a1) @ W2 (fp16)
// W packed fp16, FRAGMENT-MAJOR (see wpack_kernel)
__device__ unsigned g_W1p[(IN_CH / 2) * HID_CH];
__device__ unsigned g_W2p[(HID_CH / 2) * OUT_CH];
__device__ int      g_is64;

// ---------------- prep: zero counters + dtype detect ------------------------
__global__ void zero_detect_kernel(const unsigned* __restrict__ w) {
    int n = blockIdx.x * blockDim.x + threadIdx.x;
    if (n < N_NODES) g_cnt[n] = 0;
    if (n == 0) {
        int is64 = 1;
        for (int i = 0; i < 64; i++)
            if (w[2 * i + 1] != 0u) { is64 = 0; break; }
        g_is64 = is64;
    }
}

// 4 edges per thread (R12 version — best measured)
__global__ void count_deg_kernel(const void* __restrict__ ei) {
    int t = blockIdx.x * blockDim.x + threadIdx.x;
    if (t >= N_EDGES / 4) return;
    int d0, d1, d2, d3;
    if (g_is64) {
        const longlong2* p =
            (const longlong2*)((const long long*)ei + N_EDGES);
        longlong2 a = p[2 * t], b = p[2 * t + 1];
        d0 = (int)a.x; d1 = (int)a.y; d2 = (int)b.x; d3 = (int)b.y;
    } else {
        const int4* p = (const int4*)((const int*)ei + N_EDGES);
        int4 a = p[t];
        d0 = a.x; d1 = a.y; d2 = a.z; d3 = a.w;
    }
    atomicAdd(&g_cnt[d0], 1);
    atomicAdd(&g_cnt[d1], 1);
    atomicAdd(&g_cnt[d2], 1);
    atomicAdd(&g_cnt[d3], 1);
}

// ---------------- W pack: fp16, fragment-major layout ------------------------
// dest index: chunk*(16*NC) + (n>>3)*128 + ks*64 + ((n&7)*4 + t4)*2 + j
//   where k2 in chunk: w = k2&15, ks = w>>3, j = (w>>2)&1, t4 = w&3.
__global__ void wpack_kernel(const float* __restrict__ W1,
                             const float* __restrict__ W2) {
    int i = blockIdx.x * blockDim.x + threadIdx.x;
    if (i < (IN_CH / 2) * HID_CH) {
        int k2 = i / HID_CH, n = i % HID_CH;
        float w0 = W1[(size_t)(2 * k2) * HID_CH + n];
        float w1 = W1[(size_t)(2 * k2 + 1) * HID_CH + n];
        __half2 p = __floats2half2_rn(w0, w1);
        int chunk = k2 >> 4, w = k2 & 15;
        int ks = w >> 3, j = (w >> 2) & 1, t4 = w & 3;
        int idx = chunk * (16 * HID_CH) + (n >> 3) * 128 + ks * 64 +
                  ((n & 7) * 4 + t4) * 2 + j;
        g_W1p[idx] = *reinterpret_cast<unsigned*>(&p);
    }
    if (i < (HID_CH / 2) * OUT_CH) {
        int k2 = i / OUT_CH, n = i % OUT_CH;
        float w0 = W2[(size_t)(2 * k2) * OUT_CH + n];
        float w1 = W2[(size_t)(2 * k2 + 1) * OUT_CH + n];
        __half2 p = __floats2half2_rn(w0, w1);
        int chunk = k2 >> 4, w = k2 & 15;
        int ks = w >> 3, j = (w >> 2) & 1, t4 = w & 3;
        int idx = chunk * (16 * OUT_CH) + (n >> 3) * 128 + ks * 64 +
                  ((n & 7) * 4 + t4) * 2 + j;
        g_W2p[idx] = *reinterpret_cast<unsigned*>(&p);
    }
}

// ---------------- scans (dinv fused into scan1; scan2 fused into scan23) ----
__global__ void scan1_kernel() {
    __shared__ int sm[256];
    int tid = threadIdx.x;
    int i = blockIdx.x * 256 + tid;
    int v = (i < N_NODES) ? g_cnt[i] : 0;
    if (i < N_NODES) g_dinv[i] = rsqrtf((float)(v + 1));   // +1 self-loop
    sm[tid] = v;
    __syncthreads();
#pragma unroll
    for (int off = 1; off < 256; off <<= 1) {
        int t = (tid >= off) ? sm[tid - off] : 0;
        __syncthreads();
        sm[tid] += t;
        __syncthreads();
    }
    if (i < N_NODES) g_rowstart[i] = sm[tid] - v;
    if (tid == 255) g_part[blockIdx.x] = sm[tid];
}

__global__ void scan23_kernel() {
    __shared__ int sm[256];
    int tid = threadIdx.x;
    int v = 0;
    for (int i = tid; i < blockIdx.x; i += 256) v += g_part[i];
    sm[tid] = v;
    __syncthreads();
#pragma unroll
    for (int off = 128; off > 0; off >>= 1) {
        if (tid < off) sm[tid] += sm[tid + off];
        __syncthreads();
    }
    int base = sm[0];
    int i = blockIdx.x * 256 + tid;
    if (i < N_NODES) {
        int r = g_rowstart[i] + base;
        g_rowstart[i] = r;
        g_cursor[i] = r;
    }
}

// ---------------- CSR fill (2 edges per thread, R12 version) -----------------
__global__ void fill_csr_kernel(const void* __restrict__ ei) {
    int t = blockIdx.x * blockDim.x + threadIdx.x;
    if (t >= N_EDGES / 2) return;
    int s0, d0, s1, d1;
    if (g_is64) {
        const longlong2* ps = (const longlong2*)ei;
        const longlong2* pd = (const longlong2*)((const long long*)ei + N_EDGES);
        longlong2 a = ps[t], b = pd[t];
        s0 = (int)a.x; s1 = (int)a.y;
        d0 = (int)b.x; d1 = (int)b.y;
    } else {
        const int2* ps = (const int2*)ei;
        const int2* pd = (const int2*)((const int*)ei + N_EDGES);
        int2 a = ps[t], b = pd[t];
        s0 = a.x; s1 = a.y;
        d0 = b.x; d1 = b.y;
    }
    float w0 = g_dinv[s0] * g_dinv[d0];
    float w1 = g_dinv[s1] * g_dinv[d1];
    int slot0 = atomicAdd(&g_cursor[d0], 1);
    g_csr[slot0] = make_int2(s0, __float_as_int(w0));
    int slot1 = atomicAdd(&g_cursor[d1], 1);
    g_csr[slot1] = make_int2(s1, __float_as_int(w1));
}

// ---------------- tensor-core mma helper -------------------------------------
__device__ __forceinline__ void mma_f16(float* c, const unsigned* a,
                                        unsigned b0, unsigned b1) {
    asm volatile(
        "mma.sync.aligned.m16n8k16.row.col.f32.f16.f16.f32 "
        "{%0,%1,%2,%3},{%4,%5,%6,%7},{%8,%9},{%0,%1,%2,%3};"
        : "+f"(c[0]), "+f"(c[1]), "+f"(c[2]), "+f"(c[3])
        : "r"(a[0]), "r"(a[1]), "r"(a[2]), "r"(a[3]), "r"(b0), "r"(b1));
}

// ---------------- GEMM1: h1(fp16) = x(fp32) @ W1 (frag-major B) --------------
__global__ __launch_bounds__(256)
void gemm1_kernel(const float* __restrict__ A,
                  const unsigned* __restrict__ Wp,
                  __half* __restrict__ out, int M) {
    constexpr int K = IN_CH, NC = HID_CH;
    constexpr int STRIDE = 20;
    constexpr int WARPS_M = 4;      // WARPS_N = 2
    constexpr int MT = 2;
    constexpr int BWORDS = 16 * NC; // 2048 words per chunk

    __shared__ unsigned As[128 * STRIDE];
    __shared__ unsigned Bs[BWORDS];

    int tid = threadIdx.x, wid = tid >> 5, lane = tid & 31;
    int g = lane >> 2, t4 = lane & 3;
    int warp_m = (wid % WARPS_M) * (MT * 16);
    int warp_n = (wid / WARPS_M) * 64;
    int bct0 = warp_n >> 3;
    int m0 = blockIdx.x * 128;

    float acc[MT][8][4];
#pragma unroll
    for (int mt = 0; mt < MT; mt++)
#pragma unroll
        for (int nt = 0; nt < 8; nt++)
#pragma unroll
            for (int i = 0; i < 4; i++) acc[mt][nt][i] = 0.0f;

    for (int kk = 0; kk < K; kk += 32) {
#pragma unroll
        for (int i = 0; i < 4; i++) {
            int idx = i * 256 + tid;
            int r = idx >> 3, c4 = idx & 7;
            int gm = m0 + r;
            uint2 w = make_uint2(0u, 0u);
            if (gm < M) {
                float4 v = *(const float4*)(A + (size_t)gm * K + kk + c4 * 4);
                __half2 p0 = __floats2half2_rn(v.x, v.y);
                __half2 p1 = __floats2half2_rn(v.z, v.w);
                w.x = *reinterpret_cast<unsigned*>(&p0);
                w.y = *reinterpret_cast<unsigned*>(&p1);
            }
            *(uint2*)&As[r * STRIDE + c4 * 2] = w;
        }
        {
            const uint4* wp = (const uint4*)(Wp + (size_t)(kk >> 5) * BWORDS);
            uint4* bs = (uint4*)Bs;
            bs[tid]       = wp[tid];
            bs[tid + 256] = wp[tid + 256];
        }
        __syncthreads();

#pragma unroll
        for (int ks = 0; ks < 2; ks++) {
            unsigned a[MT][4];
#pragma unroll
            for (int mt = 0; mt < MT; mt++) {
                int r0 = (warp_m + mt * 16 + g) * STRIDE + ks * 8 + t4;
                int r1 = (warp_m + mt * 16 + g + 8) * STRIDE + ks * 8 + t4;
                a[mt][0] = As[r0];     a[mt][1] = As[r1];
                a[mt][2] = As[r0 + 4]; a[mt][3] = As[r1 + 4];
            }
#pragma unroll
            for (int nt = 0; nt < 8; nt++) {
                uint2 b = *(const uint2*)&Bs[(bct0 + nt) * 128 + ks * 64 + lane * 2];
#pragma unroll
                for (int mt = 0; mt < MT; mt++)
                    mma_f16(acc[mt][nt], a[mt], b.x, b.y);
            }
        }
        __syncthreads();
    }

#pragma unroll
    for (int mt = 0; mt < MT; mt++) {
        int r0 = m0 + warp_m + mt * 16 + g;
        int r1 = r0 + 8;
#pragma unroll
        for (int nt = 0; nt < 8; nt++) {
            int col = warp_n + nt * 8 + t4 * 2;
            if (r0 < M)
                *(__half2*)(out + (size_t)r0 * NC + col) =
                    __floats2half2_rn(acc[mt][nt][0], acc[mt][nt][1]);
            if (r1 < M)
                *(__half2*)(out + (size_t)r1 * NC + col) =
                    __floats2half2_rn(acc[mt][nt][2], acc[mt][nt][3]);
        }
    }
}

// ---------------- 8x fp16 -> 8x fp32 unpack ----------------------------------
__device__ __forceinline__ void h8_acc(uint4 u, float w, float* acc) {
    float2 f0 = __half22float2(*reinterpret_cast<__half2*>(&u.x));
    float2 f1 = __half22float2(*reinterpret_cast<__half2*>(&u.y));
    float2 f2 = __half22float2(*reinterpret_cast<__half2*>(&u.z));
    float2 f3 = __half22float2(*reinterpret_cast<__half2*>(&u.w));
    acc[0] += w * f0.x; acc[1] += w * f0.y;
    acc[2] += w * f1.x; acc[3] += w * f1.y;
    acc[4] += w * f2.x; acc[5] += w * f2.y;
    acc[6] += w * f3.x; acc[7] += w * f3.y;
}

// ---------------- FUSED: agg1 (CSR) + relu + GEMM2 --------------------------
__global__ __launch_bounds__(256)
void agg1_gemm2_kernel(const float* __restrict__ b1,
                       const unsigned* __restrict__ Wp,
                       __half* __restrict__ out, int M) {
    constexpr int STRIDE = 20;
    constexpr int NC = OUT_CH;      // 64
    constexpr int BWORDS = 16 * NC; // 1024 words per chunk

    __shared__ unsigned As[4][128 * STRIDE];
    __shared__ unsigned Bs[BWORDS];

    int tid = threadIdx.x, wid = tid >> 5, lane = tid & 31;
    int g = lane >> 2, t4 = lane & 3;
    int m0 = blockIdx.x * 128;

    int half = lane >> 4;
    int hl   = lane & 15;
    float4 bA = ((const float4*)b1)[2 * hl];
    float4 bB = ((const float4*)b1)[2 * hl + 1];
    int chunk = hl >> 2;
    int word  = (hl & 3) * 4;

#pragma unroll 1
    for (int i = 0; i < 8; i++) {
        int r = wid * 16 + i * 2 + half;
        int node = m0 + r;
        uint4 u = make_uint4(0u, 0u, 0u, 0u);
        if (node < M) {
            int beg = g_rowstart[node];
            int cnt = g_cnt[node];
            float acc[8];
#pragma unroll
            for (int k = 0; k < 8; k++) acc[k] = 0.0f;
            int j = 0;
            for (; j + 7 < cnt; j += 8) {
                int2 e[8];
                uint4 v[8];
#pragma unroll
                for (int q = 0; q < 8; q++)
                    e[q] = __ldg(&g_csr[beg + j + q]);
#pragma unroll
                for (int q = 0; q < 8; q++)
                    v[q] = __ldg((const uint4*)(g_h1h + (size_t)e[q].x * HID_CH) + hl);
#pragma unroll
                for (int q = 0; q < 8; q++)
                    h8_acc(v[q], __int_as_float(e[q].y), acc);
            }
            for (; j + 3 < cnt; j += 4) {
                int2 e0 = __ldg(&g_csr[beg + j]);
                int2 e1 = __ldg(&g_csr[beg + j + 1]);
                int2 e2 = __ldg(&g_csr[beg + j + 2]);
                int2 e3 = __ldg(&g_csr[beg + j + 3]);
                uint4 v0 = __ldg((const uint4*)(g_h1h + (size_t)e0.x * HID_CH) + hl);
                uint4 v1 = __ldg((const uint4*)(g_h1h + (size_t)e1.x * HID_CH) + hl);
                uint4 v2 = __ldg((const uint4*)(g_h1h + (size_t)e2.x * HID_CH) + hl);
                uint4 v3 = __ldg((const uint4*)(g_h1h + (size_t)e3.x * HID_CH) + hl);
                h8_acc(v0, __int_as_float(e0.y), acc);
                h8_acc(v1, __int_as_float(e1.y), acc);
                h8_acc(v2, __int_as_float(e2.y), acc);
                h8_acc(v3, __int_as_float(e3.y), acc);
            }
            for (; j < cnt; j++) {
                int2 e = __ldg(&g_csr[beg + j]);
                uint4 v = __ldg((const uint4*)(g_h1h + (size_t)e.x * HID_CH) + hl);
                h8_acc(v, __int_as_float(e.y), acc);
            }
            float di = g_dinv[node];
            float sw = di * di;
            uint4 hv = *((const uint4*)(g_h1h + (size_t)node * HID_CH) + hl);
            h8_acc(hv, sw, acc);
            acc[0] = fmaxf(acc[0] + bA.x, 0.f);
            acc[1] = fmaxf(acc[1] + bA.y, 0.f);
            acc[2] = fmaxf(acc[2] + bA.z, 0.f);
            acc[3] = fmaxf(acc[3] + bA.w, 0.f);
            acc[4] = fmaxf(acc[4] + bB.x, 0.f);
            acc[5] = fmaxf(acc[5] + bB.y, 0.f);
            acc[6] = fmaxf(acc[6] + bB.z, 0.f);
            acc[7] = fmaxf(acc[7] + bB.w, 0.f);
            __half2 p0 = __floats2half2_rn(acc[0], acc[1]);
            __half2 p1 = __floats2half2_rn(acc[2], acc[3]);
            __half2 p2 = __floats2half2_rn(acc[4], acc[5]);
            __half2 p3 = __floats2half2_rn(acc[6], acc[7]);
            u.x = *reinterpret_cast<unsigned*>(&p0);
            u.y = *reinterpret_cast<unsigned*>(&p1);
            u.z = *reinterpret_cast<unsigned*>(&p2);
            u.w = *reinterpret_cast<unsigned*>(&p3);
        }
        *(uint4*)&As[chunk][r * STRIDE + word] = u;
    }
    __syncthreads();

    // ---- phase 2: GEMM vs W2 (frag-major B) ----
    int warp_m = wid * 16;
    float acc[8][4];
#pragma unroll
    for (int nt = 0; nt < 8; nt++)
#pragma unroll
        for (int i = 0; i < 4; i++) acc[nt][i] = 0.0f;

#pragma unroll
    for (int c = 0; c < 4; c++) {
        {
            const uint4* wp = (const uint4*)(Wp + (size_t)c * BWORDS);
            ((uint4*)Bs)[tid] = wp[tid];
        }
        __syncthreads();

#pragma unroll
        for (int ks = 0; ks < 2; ks++) {
            unsigned a[4];
            int r0 = (warp_m + g) * STRIDE + ks * 8 + t4;
            int r1 = (warp_m + g + 8) * STRIDE + ks * 8 + t4;
            a[0] = As[c][r0];     a[1] = As[c][r1];
            a[2] = As[c][r0 + 4]; a[3] = As[c][r1 + 4];
#pragma unroll
            for (int nt = 0; nt < 8; nt++) {
                uint2 b = *(const uint2*)&Bs[nt * 128 + ks * 64 + lane * 2];
                mma_f16(acc[nt], a, b.x, b.y);
            }
        }
        __syncthreads();
    }

    int r0 = m0 + warp_m + g;
    int r1 = r0 + 8;
#pragma unroll
    for (int nt = 0; nt < 8; nt++) {
        int col = nt * 8 + t4 * 2;
        if (r0 < M)
            *(__half2*)(out + (size_t)r0 * NC + col) =
                __floats2half2_rn(acc[nt][0], acc[nt][1]);
        if (r1 < M)
            *(__half2*)(out + (size_t)r1 * NC + col) =
                __floats2half2_rn(acc[nt][2], acc[nt][3]);
    }
}

// ---------------- agg2: 8 lanes/node, uint4, 8-edge unroll (R12 winner) -----
__global__ __launch_bounds__(256)
void agg2_kernel(const float* __restrict__ b2, float* __restrict__ out) {
    int t = blockIdx.x * blockDim.x + threadIdx.x;
    int node = t >> 3;
    int l8 = t & 7;
    if (node >= N_NODES) return;
    int beg = g_rowstart[node];
    int cnt = g_cnt[node];

    float acc[8];
#pragma unroll
    for (int k = 0; k < 8; k++) acc[k] = 0.0f;
    int j = 0;
    for (; j + 7 < cnt; j += 8) {
        int2 e[8];
        uint4 v[8];
#pragma unroll
        for (int q = 0; q < 8; q++)
            e[q] = __ldg(&g_csr[beg + j + q]);
#pragma unroll
        for (int q = 0; q < 8; q++)
            v[q] = __ldg((const uint4*)(g_h2h + (size_t)e[q].x * OUT_CH) + l8);
#pragma unroll
        for (int q = 0; q < 8; q++)
            h8_acc(v[q], __int_as_float(e[q].y), acc);
    }
    for (; j + 3 < cnt; j += 4) {
        int2 e0 = __ldg(&g_csr[beg + j]);
        int2 e1 = __ldg(&g_csr[beg + j + 1]);
        int2 e2 = __ldg(&g_csr[beg + j + 2]);
        int2 e3 = __ldg(&g_csr[beg + j + 3]);
        uint4 v0 = __ldg((const uint4*)(g_h2h + (size_t)e0.x * OUT_CH) + l8);
        uint4 v1 = __ldg((const uint4*)(g_h2h + (size_t)e1.x * OUT_CH) + l8);
        uint4 v2 = __ldg((const uint4*)(g_h2h + (size_t)e2.x * OUT_CH) + l8);
        uint4 v3 = __ldg((const uint4*)(g_h2h + (size_t)e3.x * OUT_CH) + l8);
        h8_acc(v0, __int_as_float(e0.y), acc);
        h8_acc(v1, __int_as_float(e1.y), acc);
        h8_acc(v2, __int_as_float(e2.y), acc);
        h8_acc(v3, __int_as_float(e3.y), acc);
    }
    for (; j < cnt; j++) {
        int2 e = __ldg(&g_csr[beg + j]);
        uint4 v = __ldg((const uint4*)(g_h2h + (size_t)e.x * OUT_CH) + l8);
        h8_acc(v, __int_as_float(e.y), acc);
    }
    float di = g_dinv[node];
    float sw = di * di;
    uint4 hv = *((const uint4*)(g_h2h + (size_t)node * OUT_CH) + l8);
    h8_acc(hv, sw, acc);
    float4 bA = ((const float4*)b2)[2 * l8];
    float4 bB = ((const float4*)b2)[2 * l8 + 1];
    float4 o0 = make_float4(acc[0] + bA.x, acc[1] + bA.y,
                            acc[2] + bA.z, acc[3] + bA.w);
    float4 o1 = make_float4(acc[4] + bB.x, acc[5] + bB.y,
                            acc[6] + bB.z, acc[7] + bB.w);
    float* dst = out + (size_t)node * OUT_CH + l8 * 8;
    *(float4*)dst = o0;
    *(float4*)(dst + 4) = o1;
}

// ---------------- launch (R12 structure) --------------------------------------
extern "C" void kernel_launch(void* const* d_in, const int* in_sizes, int n_in,
                              void* d_out, int out_size) {
    const float* x  = (const float*)d_in[0];
    const void*  ei = d_in[1];
    const float* W1 = (const float*)d_in[2];
    const float* b1 = (const float*)d_in[3];
    const float* W2 = (const float*)d_in[4];
    const float* b2 = (const float*)d_in[5];
    float* out = (float*)d_out;

    __half *p_h1h, *p_h2h;
    unsigned *p_W1p, *p_W2p;
    cudaGetSymbolAddress((void**)&p_h1h, g_h1h);
    cudaGetSymbolAddress((void**)&p_h2h, g_h2h);
    cudaGetSymbolAddress((void**)&p_W1p, g_W1p);
    cudaGetSymbolAddress((void**)&p_W2p, g_W2p);

    static cudaStream_t s_side = nullptr;
    static cudaEvent_t  s_fork = nullptr, s_join = nullptr;
    if (s_side == nullptr) {
        cudaStreamCreateWithFlags(&s_side, cudaStreamNonBlocking);
        cudaEventCreateWithFlags(&s_fork, cudaEventDisableTiming);
        cudaEventCreateWithFlags(&s_join, cudaEventDisableTiming);
    }

    // ---- fork: CSR-build branch concurrent with wpack + GEMM1 ----
    cudaEventRecord(s_fork, 0);
    cudaStreamWaitEvent(s_side, s_fork, 0);

    // side branch fully enqueued first (R12 order)
    zero_detect_kernel<<<NB_SCAN, 256, 0, s_side>>>((const unsigned*)ei);
    count_deg_kernel<<<(N_EDGES / 4 + 255) / 256, 256, 0, s_side>>>(ei);
    scan1_kernel<<<NB_SCAN, 256, 0, s_side>>>();
    scan23_kernel<<<NB_SCAN, 256, 0, s_side>>>();
    fill_csr_kernel<<<(N_EDGES / 2 + 255) / 256, 256, 0, s_side>>>(ei);
    cudaEventRecord(s_join, s_side);

    wpack_kernel<<<((IN_CH / 2) * HID_CH + 255) / 256, 256>>>(W1, W2);
    gemm1_kernel<<<(N_NODES + 127) / 128, 256>>>(x, p_W1p, p_h1h, N_NODES);

    cudaStreamWaitEvent(0, s_join, 0);

    // fused agg1 + relu + GEMM2 -> h2
    agg1_gemm2_kernel<<<(N_NODES + 127) / 128, 256>>>(b1, p_W2p, p_h2h, N_NODES);
    // final aggregation -> out
    agg2_kernel<<<(N_NODES * 8 + 255) / 256, 256>>>(b2, out);
}